// round 16
// baseline (speedup 1.0000x reference)
#include <cuda_runtime.h>
#include <cuda_fp16.h>
#include <cstdint>

#define DINLINE __device__ __forceinline__

static constexpr int B_ROWS = 4096;
static constexpr int D_DIM  = 256;
static constexpr int N_TOT  = 8192;
static constexpr int TILE   = 128;
static constexpr int NCTA   = 148;
static constexpr int TILES_PER_CTA = 14;     // 148*14 = 2072 of 2080
// leftover 8 tiles (strip 32, jt 56..63) -> 32 column-quarter items

static constexpr float EXP_K = 2.8853900817779268f;  // 2/ln(2)

// ---- device scratch ----
__device__ __align__(16) __half g_Z[N_TOT * D_DIM];
__device__ float g_denom[N_TOT];

// ============ helpers ============
DINLINE uint32_t smem_u32(const void* p) {
    uint32_t a;
    asm("{ .reg .u64 t; cvta.to.shared.u64 t, %1; cvt.u32.u64 %0, t; }" : "=r"(a) : "l"(p));
    return a;
}
DINLINE void ldsm_x4(uint32_t addr, uint32_t* r) {
    asm volatile("ldmatrix.sync.aligned.m8n8.x4.shared.b16 {%0,%1,%2,%3}, [%4];"
                 : "=r"(r[0]), "=r"(r[1]), "=r"(r[2]), "=r"(r[3]) : "r"(addr));
}
DINLINE void mma16816(float4& c, const uint32_t* a, uint32_t b0, uint32_t b1) {
    asm volatile(
        "mma.sync.aligned.m16n8k16.row.col.f32.f16.f16.f32 "
        "{%0,%1,%2,%3}, {%4,%5,%6,%7}, {%8,%9}, {%0,%1,%2,%3};"
        : "+f"(c.x), "+f"(c.y), "+f"(c.z), "+f"(c.w)
        : "r"(a[0]), "r"(a[1]), "r"(a[2]), "r"(a[3]), "r"(b0), "r"(b1));
}
DINLINE float ex2f(float x) {
    float e;
    asm("ex2.approx.f32 %0, %1;" : "=f"(e) : "f"(x));
    return e;
}
// PDL intrinsics (base sm_90 PTX; family-target safe)
DINLINE void pdl_trigger() {
    asm volatile("griddepcontrol.launch_dependents;" ::: "memory");
}
DINLINE void pdl_wait() {
    asm volatile("griddepcontrol.wait;" ::: "memory");
}
// pair-major triangle enumeration: tile t -> (strip it, first col-tile jt0, run end)
DINLINE void decode(int t, int& it, int& jt0, int& runend) {
    const int P = t / 65;
    const int r = t - P * 65;
    if (r < 64 - P) { it = P;      jt0 = P + r;                   runend = t + (64 - P - r); }
    else            { it = 63 - P; jt0 = (63 - P) + r - (64 - P); runend = t + (65 - r); }
}

// ============ SMEM layout: 3 rotating tile buffers ============
static constexpr int ROW_BYTES  = 528;               // 256 fp16 + 16B pad
static constexpr int TILE_BYTES = 128 * ROW_BYTES;   // 67584 (1024-aligned)
static constexpr int SMEM_TOTAL = 3 * TILE_BYTES;    // 202752

DINLINE void load_tile(uint32_t smem_dst, const __half* gsrc, int tid) {
#pragma unroll
    for (int i = 0; i < 16; ++i) {
        int u = tid + i * 256;
        int r = u >> 5, c = u & 31;
        uint32_t saddr = smem_dst + (uint32_t)r * ROW_BYTES + (uint32_t)c * 16;
        const char* g = (const char*)gsrc + (size_t)u * 16;
        asm volatile("cp.async.cg.shared.global [%0], [%1], 16;" :: "r"(saddr), "l"(g));
    }
}

// ============ kernel 1: normalize (row per warp) + zero denom/out; PDL trigger ============
__global__ void __launch_bounds__(256) k_normalize(const float* __restrict__ q,
                                                   const float* __restrict__ p,
                                                   float* __restrict__ out) {
    const int wid  = threadIdx.x >> 5;
    const int lane = threadIdx.x & 31;
    const int row  = blockIdx.x * 8 + wid;
    if (threadIdx.x < 8) g_denom[blockIdx.x * 8 + threadIdx.x] = 0.0f;
    if (blockIdx.x == 0 && threadIdx.x == 0) out[0] = 0.0f;

    const float* src = (row < B_ROWS) ? q + (size_t)row * D_DIM
                                      : p + (size_t)(row - B_ROWS) * D_DIM;
    float4 v0 = ((const float4*)src)[lane * 2];
    float4 v1 = ((const float4*)src)[lane * 2 + 1];
    float ss = v0.x * v0.x + v0.y * v0.y + v0.z * v0.z + v0.w * v0.w
             + v1.x * v1.x + v1.y * v1.y + v1.z * v1.z + v1.w * v1.w;
#pragma unroll
    for (int o = 16; o; o >>= 1) ss += __shfl_xor_sync(0xffffffffu, ss, o);
    float inv = 1.0f / fmaxf(sqrtf(ss), 1e-12f);

    __half2 h[4];
    h[0] = __floats2half2_rn(v0.x * inv, v0.y * inv);
    h[1] = __floats2half2_rn(v0.z * inv, v0.w * inv);
    h[2] = __floats2half2_rn(v1.x * inv, v1.y * inv);
    h[3] = __floats2half2_rn(v1.z * inv, v1.w * inv);
    ((uint4*)(g_Z + (size_t)row * D_DIM))[lane] = *(const uint4*)h;
    pdl_trigger();   // release dependent gemm launch as early as possible
}

// ============ kernel 2: upper-triangle Gram, 3-buffer ring, 1 sync/tile, direct REDG ============
__global__ void __launch_bounds__(256, 1) k_gemm_denom() {
    extern __shared__ __align__(1024) char smem[];
    const int tid    = threadIdx.x;
    const int wid    = tid >> 5;
    const int lane   = tid & 31;
    const int warp_m = wid & 3;
    const int warp_n = wid >> 2;
    uint32_t sbase = smem_u32(smem);

    const uint32_t lrow = (uint32_t)(lane & 15) * ROW_BYTES + (uint32_t)(lane >> 4) * 16;
    const uint32_t aoff = (uint32_t)(warp_m * 32) * ROW_BYTES + lrow;
    const uint32_t boff = (uint32_t)(warp_n * 64) * ROW_BYTES + lrow;

    const int t0 = blockIdx.x * TILES_PER_CTA;
    const int t1 = t0 + TILES_PER_CTA;

    // prologue setup overlaps the normalize tail; wait before touching g_Z
    int it, jt0, runend;
    decode(t0, it, jt0, runend);
    pdl_wait();

    int nb = 0, abuf, bb0;
    abuf = nb; load_tile(sbase + (uint32_t)nb * TILE_BYTES, g_Z + (size_t)it * TILE * D_DIM, tid);  nb = (nb + 1) % 3;
    bb0  = nb; load_tile(sbase + (uint32_t)nb * TILE_BYTES, g_Z + (size_t)jt0 * TILE * D_DIM, tid); nb = (nb + 1) % 3;
    asm volatile("cp.async.commit_group;" ::: "memory");

    int t = t0;
#pragma unroll 1
    while (t < t1) {
        decode(t, it, jt0, runend);
        const int n = min(t1, runend) - t;

        // A (and B0) for this run were prefetched; make them visible
        asm volatile("cp.async.wait_group 0;" ::: "memory");
        __syncthreads();

        // hoist A fragments for the whole run into registers (frees the A buffer)
        uint32_t areg[16][8];
        {
            const uint32_t abase = sbase + (uint32_t)abuf * TILE_BYTES + aoff;
#pragma unroll
            for (int ks = 0; ks < 16; ++ks) {
                ldsm_x4(abase + (uint32_t)ks * 32, areg[ks]);
                ldsm_x4(abase + 16u * ROW_BYTES + (uint32_t)ks * 32, areg[ks] + 4);
            }
        }

        float rsum[2][2] = {{0.f, 0.f}, {0.f, 0.f}};
        int bcur = bb0;

#pragma unroll 1
        for (int idx = 0; idx < n; ++idx) {
            const int jt = jt0 + idx;
            if (idx + 1 < n) {
                // prefetch next B; single sync per tile
                load_tile(sbase + (uint32_t)nb * TILE_BYTES,
                          g_Z + (size_t)(jt + 1) * TILE * D_DIM, tid);
                nb = (nb + 1) % 3;
                asm volatile("cp.async.commit_group;" ::: "memory");
                asm volatile("cp.async.wait_group 1;" ::: "memory");
                __syncthreads();
            } else {
                // last tile of run: drain, sync, then prefetch next run's A+B0
                asm volatile("cp.async.wait_group 0;" ::: "memory");
                __syncthreads();
                if (t + n < t1) {
                    int it2, jt02, re2;
                    decode(t + n, it2, jt02, re2);
                    abuf = nb; load_tile(sbase + (uint32_t)nb * TILE_BYTES,
                                         g_Z + (size_t)it2 * TILE * D_DIM, tid);  nb = (nb + 1) % 3;
                    bb0  = nb; load_tile(sbase + (uint32_t)nb * TILE_BYTES,
                                         g_Z + (size_t)jt02 * TILE * D_DIM, tid); nb = (nb + 1) % 3;
                    asm volatile("cp.async.commit_group;" ::: "memory");
                }
            }

            const uint32_t bbase = sbase + (uint32_t)bcur * TILE_BYTES + boff;
            bcur = (bcur + 1) % 3;   // B tiles within a run rotate strictly +1

            float4 acc[2][8];
#pragma unroll
            for (int mi = 0; mi < 2; ++mi)
#pragma unroll
                for (int nt = 0; nt < 8; ++nt) acc[mi][nt] = make_float4(0.f, 0.f, 0.f, 0.f);

#pragma unroll
            for (int ks = 0; ks < 16; ++ks) {
                uint32_t bf[4][4];
#pragma unroll
                for (int bt = 0; bt < 4; ++bt)
                    ldsm_x4(bbase + (uint32_t)(bt * 16) * ROW_BYTES + (uint32_t)ks * 32, bf[bt]);
#pragma unroll
                for (int bt = 0; bt < 4; ++bt) {
                    mma16816(acc[0][2 * bt],     areg[ks],     bf[bt][0], bf[bt][2]);
                    mma16816(acc[0][2 * bt + 1], areg[ks],     bf[bt][1], bf[bt][3]);
                    mma16816(acc[1][2 * bt],     areg[ks] + 4, bf[bt][0], bf[bt][2]);
                    mma16816(acc[1][2 * bt + 1], areg[ks] + 4, bf[bt][1], bf[bt][3]);
                }
            }

            // epilogue (no barrier: warps drift; MUFU overlaps other warps' MMA)
            const bool offdiag = (jt != it);
            float colacc[16];
#pragma unroll
            for (int i = 0; i < 16; ++i) colacc[i] = 0.f;
#pragma unroll
            for (int mi = 0; mi < 2; ++mi) {
                float s0 = 0.f, s1 = 0.f;
#pragma unroll
                for (int nt = 0; nt < 8; ++nt) {
                    float4 c = acc[mi][nt];
                    float ex = ex2f(c.x * EXP_K), ey = ex2f(c.y * EXP_K);
                    float ez = ex2f(c.z * EXP_K), ew = ex2f(c.w * EXP_K);
                    s0 += ex + ey;
                    s1 += ez + ew;
                    colacc[nt * 2]     += ex + ez;
                    colacc[nt * 2 + 1] += ey + ew;
                }
                rsum[mi][0] += s0;
                rsum[mi][1] += s1;
            }
            if (offdiag) {
#pragma unroll
                for (int i = 0; i < 16; ++i) {
                    float v = colacc[i];
                    v += __shfl_xor_sync(0xffffffffu, v, 4);
                    v += __shfl_xor_sync(0xffffffffu, v, 8);
                    v += __shfl_xor_sync(0xffffffffu, v, 16);
                    colacc[i] = v;
                }
                if (lane < 4) {
                    const int cbase = jt * TILE + warp_n * 64;
#pragma unroll
                    for (int nt = 0; nt < 8; ++nt) {
                        atomicAdd(&g_denom[cbase + nt * 8 + 2 * lane],     colacc[nt * 2]);
                        atomicAdd(&g_denom[cbase + nt * 8 + 2 * lane + 1], colacc[nt * 2 + 1]);
                    }
                }
            }
        }

        // run row sums: intra-warp reduce + direct REDG (both warp_n contribute)
#pragma unroll
        for (int mi = 0; mi < 2; ++mi)
#pragma unroll
            for (int h = 0; h < 2; ++h) {
                float v = rsum[mi][h];
                v += __shfl_xor_sync(0xffffffffu, v, 1);
                v += __shfl_xor_sync(0xffffffffu, v, 2);
                if ((lane & 3) == 0)
                    atomicAdd(&g_denom[it * TILE + warp_m * 32 + mi * 16 + h * 8 + (lane >> 2)], v);
            }

        t += n;
    }

    // ---- leftover quarter-tile pass: CTAs 0..31, strip 32, jt 56..63, 32 cols each ----
    if (blockIdx.x < 32) {
        __syncthreads();   // last tile's B reads done before buffers are reused
        const int it2 = 32;
        const int jt  = 56 + (blockIdx.x >> 2);
        const int cq  = blockIdx.x & 3;

        load_tile(sbase, g_Z + (size_t)it2 * TILE * D_DIM, tid);
        {   // B quarter: 32 rows x 256 fp16 into buffer 1
            const __half* gsrc = g_Z + ((size_t)jt * TILE + cq * 32) * D_DIM;
#pragma unroll
            for (int i = 0; i < 4; ++i) {
                int u = tid + i * 256;
                int r2 = u >> 5, c2 = u & 31;
                uint32_t saddr = sbase + TILE_BYTES + (uint32_t)r2 * ROW_BYTES + (uint32_t)c2 * 16;
                asm volatile("cp.async.cg.shared.global [%0], [%1], 16;"
                             :: "r"(saddr), "l"((const char*)gsrc + (size_t)u * 16));
            }
        }
        asm volatile("cp.async.commit_group;" ::: "memory");
        asm volatile("cp.async.wait_group 0;"  ::: "memory");
        __syncthreads();

        uint32_t areg[16][8];
        const uint32_t abase = sbase + aoff;
#pragma unroll
        for (int ks = 0; ks < 16; ++ks) {
            ldsm_x4(abase + (uint32_t)ks * 32, areg[ks]);
            ldsm_x4(abase + 16u * ROW_BYTES + (uint32_t)ks * 32, areg[ks] + 4);
        }

        const uint32_t bq = sbase + TILE_BYTES + (uint32_t)(warp_n * 16) * ROW_BYTES + lrow;
        float4 acc[2][2];
#pragma unroll
        for (int mi = 0; mi < 2; ++mi)
#pragma unroll
            for (int nt = 0; nt < 2; ++nt) acc[mi][nt] = make_float4(0.f, 0.f, 0.f, 0.f);

#pragma unroll
        for (int ks = 0; ks < 16; ++ks) {
            uint32_t bf[4];
            ldsm_x4(bq + (uint32_t)ks * 32, bf);
            mma16816(acc[0][0], areg[ks],     bf[0], bf[2]);
            mma16816(acc[0][1], areg[ks],     bf[1], bf[3]);
            mma16816(acc[1][0], areg[ks] + 4, bf[0], bf[2]);
            mma16816(acc[1][1], areg[ks] + 4, bf[1], bf[3]);
        }

        float colacc[4] = {0.f, 0.f, 0.f, 0.f};
        float rs[2][2]  = {{0.f, 0.f}, {0.f, 0.f}};
#pragma unroll
        for (int mi = 0; mi < 2; ++mi)
#pragma unroll
            for (int nt = 0; nt < 2; ++nt) {
                float4 c = acc[mi][nt];
                float ex = ex2f(c.x * EXP_K), ey = ex2f(c.y * EXP_K);
                float ez = ex2f(c.z * EXP_K), ew = ex2f(c.w * EXP_K);
                rs[mi][0] += ex + ey;
                rs[mi][1] += ez + ew;
                colacc[nt * 2]     += ex + ez;
                colacc[nt * 2 + 1] += ey + ew;
            }
#pragma unroll
        for (int i = 0; i < 4; ++i) {
            float v = colacc[i];
            v += __shfl_xor_sync(0xffffffffu, v, 4);
            v += __shfl_xor_sync(0xffffffffu, v, 8);
            v += __shfl_xor_sync(0xffffffffu, v, 16);
            colacc[i] = v;
        }
        if (lane < 4) {
            const int cbase = jt * TILE + cq * 32 + warp_n * 16;
#pragma unroll
            for (int g = 0; g < 2; ++g) {
                atomicAdd(&g_denom[cbase + g * 8 + 2 * lane],     colacc[g * 2]);
                atomicAdd(&g_denom[cbase + g * 8 + 2 * lane + 1], colacc[g * 2 + 1]);
            }
        }
#pragma unroll
        for (int mi = 0; mi < 2; ++mi)
#pragma unroll
            for (int h = 0; h < 2; ++h) {
                float v = rs[mi][h];
                v += __shfl_xor_sync(0xffffffffu, v, 1);
                v += __shfl_xor_sync(0xffffffffu, v, 2);
                if ((lane & 3) == 0)
                    atomicAdd(&g_denom[it2 * TILE + warp_m * 32 + mi * 16 + h * 8 + (lane >> 2)], v);
            }
    }
}

// ============ kernel 3: one pair per warp; positives + self-term removal + final sum ============
__global__ void __launch_bounds__(256) k_loss_partial(float* __restrict__ out) {
    const int wid  = threadIdx.x >> 5;
    const int lane = threadIdx.x & 31;
    const int i    = blockIdx.x * 8 + wid;         // pair 0..4095 (grid 512)

    pdl_wait();   // overlap launch ramp with gemm tail; block until gemm done

    uint4 a = ((const uint4*)(g_Z + (size_t)i * D_DIM))[lane];
    uint4 b = ((const uint4*)(g_Z + (size_t)(i + B_ROWS) * D_DIM))[lane];
    const __half2* pa = (const __half2*)&a;
    const __half2* pb = (const __half2*)&b;
    float d = 0.f, saa = 0.f, sbb = 0.f;
#pragma unroll
    for (int j = 0; j < 4; ++j) {
        float2 fa = __half22float2(pa[j]);
        float2 fb = __half22float2(pb[j]);
        d   += fa.x * fb.x + fa.y * fb.y;
        saa += fa.x * fa.x + fa.y * fa.y;
        sbb += fb.x * fb.x + fb.y * fb.y;
    }
#pragma unroll
    for (int o = 16; o; o >>= 1) {
        d   += __shfl_xor_sync(0xffffffffu, d, o);
        saa += __shfl_xor_sync(0xffffffffu, saa, o);
        sbb += __shfl_xor_sync(0xffffffffu, sbb, o);
    }
    __shared__ float sacc[8];
    if (lane == 0) {
        float di = g_denom[i]          - exp2f(saa * EXP_K);
        float dj = g_denom[i + B_ROWS] - exp2f(sbb * EXP_K);
        sacc[wid] = -4.0f * d + logf(di) + logf(dj);
    }
    __syncthreads();
    if (threadIdx.x == 0) {
        float s = 0.0f;
#pragma unroll
        for (int w = 0; w < 8; ++w) s += sacc[w];
        atomicAdd(out, s * (1.0f / (float)N_TOT));
    }
}

// ============ launch ============
extern "C" void kernel_launch(void* const* d_in, const int* in_sizes, int n_in,
                              void* d_out, int out_size) {
    const float* q = (const float*)d_in[0];
    const float* p = (const float*)d_in[1];
    (void)in_sizes; (void)n_in; (void)out_size;

    static bool attr_set = false;
    if (!attr_set) {
        cudaFuncSetAttribute(k_gemm_denom, cudaFuncAttributeMaxDynamicSharedMemorySize, SMEM_TOTAL);
        attr_set = true;
    }

    k_normalize<<<N_TOT / 8, 256>>>(q, p, (float*)d_out);

    // gemm: PDL-dependent on normalize
    {
        cudaLaunchConfig_t cfg = {};
        cfg.gridDim = dim3(NCTA, 1, 1);
        cfg.blockDim = dim3(256, 1, 1);
        cfg.dynamicSmemBytes = SMEM_TOTAL;
        cfg.stream = 0;
        cudaLaunchAttribute at[1];
        at[0].id = cudaLaunchAttributeProgrammaticStreamSerialization;
        at[0].val.programmaticStreamSerializationAllowed = 1;
        cfg.attrs = at;
        cfg.numAttrs = 1;
        cudaLaunchKernelEx(&cfg, k_gemm_denom);
    }
    // loss: PDL-dependent on gemm
    {
        cudaLaunchConfig_t cfg = {};
        cfg.gridDim = dim3(512, 1, 1);
        cfg.blockDim = dim3(256, 1, 1);
        cfg.dynamicSmemBytes = 0;
        cfg.stream = 0;
        cudaLaunchAttribute at[1];
        at[0].id = cudaLaunchAttributeProgrammaticStreamSerialization;
        at[0].val.programmaticStreamSerializationAllowed = 1;
        cfg.attrs = at;
        cfg.numAttrs = 1;
        cudaLaunchKernelEx(&cfg, k_loss_partial, (float*)d_out);
    }
}

// round 17
// speedup vs baseline: 1.0310x; 1.0310x over previous
#include <cuda_runtime.h>
#include <cuda_fp16.h>
#include <cstdint>

#define DINLINE __device__ __forceinline__

static constexpr int B_ROWS = 4096;
static constexpr int D_DIM  = 256;
static constexpr int N_TOT  = 8192;
static constexpr int TILE   = 128;
static constexpr int NCTA   = 148;
static constexpr int TILES_PER_CTA = 14;     // 148*14 = 2072 of 2080
// leftover 8 tiles (strip 32, jt 56..63) -> 32 column-quarter items

// Z is stored pre-scaled by sqrt(2/ln2): sim_scaled = (2/ln2)*sim,
// so exp(2*sim) = 2^(sim_scaled) directly (no epilogue multiply).
static constexpr float SQ_EXPK   = 1.6986436f;        // sqrt(2/ln2)
static constexpr float NEG_2LN2  = -1.3862943611f;    // -4 / (2/ln2)

// ---- device scratch ----
__device__ __align__(16) __half g_Z[N_TOT * D_DIM];   // scaled unit rows
__device__ float g_denom[N_TOT];

// ============ helpers ============
DINLINE uint32_t smem_u32(const void* p) {
    uint32_t a;
    asm("{ .reg .u64 t; cvta.to.shared.u64 t, %1; cvt.u32.u64 %0, t; }" : "=r"(a) : "l"(p));
    return a;
}
DINLINE void ldsm_x4(uint32_t addr, uint32_t* r) {
    asm volatile("ldmatrix.sync.aligned.m8n8.x4.shared.b16 {%0,%1,%2,%3}, [%4];"
                 : "=r"(r[0]), "=r"(r[1]), "=r"(r[2]), "=r"(r[3]) : "r"(addr));
}
DINLINE void mma16816(float4& c, const uint32_t* a, uint32_t b0, uint32_t b1) {
    asm volatile(
        "mma.sync.aligned.m16n8k16.row.col.f32.f16.f16.f32 "
        "{%0,%1,%2,%3}, {%4,%5,%6,%7}, {%8,%9}, {%0,%1,%2,%3};"
        : "+f"(c.x), "+f"(c.y), "+f"(c.z), "+f"(c.w)
        : "r"(a[0]), "r"(a[1]), "r"(a[2]), "r"(a[3]), "r"(b0), "r"(b1));
}
DINLINE float ex2f(float x) {
    float e;
    asm("ex2.approx.f32 %0, %1;" : "=f"(e) : "f"(x));
    return e;
}
// PDL intrinsics (base sm_90 PTX; family-target safe)
DINLINE void pdl_trigger() {
    asm volatile("griddepcontrol.launch_dependents;" ::: "memory");
}
DINLINE void pdl_wait() {
    asm volatile("griddepcontrol.wait;" ::: "memory");
}
// pair-major triangle enumeration: tile t -> (strip it, first col-tile jt0, run end)
DINLINE void decode(int t, int& it, int& jt0, int& runend) {
    const int P = t / 65;
    const int r = t - P * 65;
    if (r < 64 - P) { it = P;      jt0 = P + r;                   runend = t + (64 - P - r); }
    else            { it = 63 - P; jt0 = (63 - P) + r - (64 - P); runend = t + (65 - r); }
}

// ============ SMEM layout: 3 rotating tile buffers ============
static constexpr int ROW_BYTES  = 528;               // 256 fp16 + 16B pad
static constexpr int TILE_BYTES = 128 * ROW_BYTES;   // 67584 (1024-aligned)
static constexpr int SMEM_TOTAL = 3 * TILE_BYTES;    // 202752

DINLINE void load_tile(uint32_t smem_dst, const __half* gsrc, int tid) {
#pragma unroll
    for (int i = 0; i < 16; ++i) {
        int u = tid + i * 256;
        int r = u >> 5, c = u & 31;
        uint32_t saddr = smem_dst + (uint32_t)r * ROW_BYTES + (uint32_t)c * 16;
        const char* g = (const char*)gsrc + (size_t)u * 16;
        asm volatile("cp.async.cg.shared.global [%0], [%1], 16;" :: "r"(saddr), "l"(g));
    }
}

// ============ kernel 1: normalize (row per warp, scaled by SQ_EXPK) ============
__global__ void __launch_bounds__(256) k_normalize(const float* __restrict__ q,
                                                   const float* __restrict__ p,
                                                   float* __restrict__ out) {
    const int wid  = threadIdx.x >> 5;
    const int lane = threadIdx.x & 31;
    const int row  = blockIdx.x * 8 + wid;
    if (threadIdx.x < 8) g_denom[blockIdx.x * 8 + threadIdx.x] = 0.0f;
    if (blockIdx.x == 0 && threadIdx.x == 0) out[0] = 0.0f;

    const float* src = (row < B_ROWS) ? q + (size_t)row * D_DIM
                                      : p + (size_t)(row - B_ROWS) * D_DIM;
    float4 v0 = ((const float4*)src)[lane * 2];
    float4 v1 = ((const float4*)src)[lane * 2 + 1];
    float ss = v0.x * v0.x + v0.y * v0.y + v0.z * v0.z + v0.w * v0.w
             + v1.x * v1.x + v1.y * v1.y + v1.z * v1.z + v1.w * v1.w;
#pragma unroll
    for (int o = 16; o; o >>= 1) ss += __shfl_xor_sync(0xffffffffu, ss, o);
    float inv = SQ_EXPK / fmaxf(sqrtf(ss), 1e-12f);

    __half2 h[4];
    h[0] = __floats2half2_rn(v0.x * inv, v0.y * inv);
    h[1] = __floats2half2_rn(v0.z * inv, v0.w * inv);
    h[2] = __floats2half2_rn(v1.x * inv, v1.y * inv);
    h[3] = __floats2half2_rn(v1.z * inv, v1.w * inv);
    ((uint4*)(g_Z + (size_t)row * D_DIM))[lane] = *(const uint4*)h;
    pdl_trigger();   // release dependent gemm launch as early as possible
}

// ============ kernel 2: upper-triangle Gram, 3-buffer ring, 1 sync/tile, direct REDG ============
__global__ void __launch_bounds__(256, 1) k_gemm_denom() {
    extern __shared__ __align__(1024) char smem[];
    const int tid    = threadIdx.x;
    const int wid    = tid >> 5;
    const int lane   = tid & 31;
    const int warp_m = wid & 3;
    const int warp_n = wid >> 2;
    uint32_t sbase = smem_u32(smem);

    const uint32_t lrow = (uint32_t)(lane & 15) * ROW_BYTES + (uint32_t)(lane >> 4) * 16;
    const uint32_t aoff = (uint32_t)(warp_m * 32) * ROW_BYTES + lrow;
    const uint32_t boff = (uint32_t)(warp_n * 64) * ROW_BYTES + lrow;

    const int t0 = blockIdx.x * TILES_PER_CTA;
    const int t1 = t0 + TILES_PER_CTA;
    const bool has_quarter = (blockIdx.x < 32);

    // prologue setup overlaps the normalize tail; wait before touching g_Z
    int it, jt0, runend;
    decode(t0, it, jt0, runend);
    pdl_wait();

    int nb = 0, abuf, bb0;
    abuf = nb; load_tile(sbase + (uint32_t)nb * TILE_BYTES, g_Z + (size_t)it * TILE * D_DIM, tid);  nb = (nb + 1) % 3;
    bb0  = nb; load_tile(sbase + (uint32_t)nb * TILE_BYTES, g_Z + (size_t)jt0 * TILE * D_DIM, tid); nb = (nb + 1) % 3;
    asm volatile("cp.async.commit_group;" ::: "memory");

    int qa = 0, qb = 1;   // buffers holding the leftover quarter's A / B (set below)

    int t = t0;
#pragma unroll 1
    while (t < t1) {
        decode(t, it, jt0, runend);
        const int n = min(t1, runend) - t;

        // A (and B0) for this run were prefetched; make them visible
        asm volatile("cp.async.wait_group 0;" ::: "memory");
        __syncthreads();

        // hoist A fragments for the whole run into registers (frees the A buffer)
        uint32_t areg[16][8];
        {
            const uint32_t abase = sbase + (uint32_t)abuf * TILE_BYTES + aoff;
#pragma unroll
            for (int ks = 0; ks < 16; ++ks) {
                ldsm_x4(abase + (uint32_t)ks * 32, areg[ks]);
                ldsm_x4(abase + 16u * ROW_BYTES + (uint32_t)ks * 32, areg[ks] + 4);
            }
        }

        float rsum[2][2] = {{0.f, 0.f}, {0.f, 0.f}};
        int bcur = bb0;

#pragma unroll 1
        for (int idx = 0; idx < n; ++idx) {
            const int jt = jt0 + idx;
            if (idx + 1 < n) {
                // prefetch next B; single sync per tile
                load_tile(sbase + (uint32_t)nb * TILE_BYTES,
                          g_Z + (size_t)(jt + 1) * TILE * D_DIM, tid);
                nb = (nb + 1) % 3;
                asm volatile("cp.async.commit_group;" ::: "memory");
                asm volatile("cp.async.wait_group 1;" ::: "memory");
                __syncthreads();
            } else {
                // last tile of run: drain, sync, then prefetch next work
                asm volatile("cp.async.wait_group 0;" ::: "memory");
                __syncthreads();
                if (t + n < t1) {
                    int it2, jt02, re2;
                    decode(t + n, it2, jt02, re2);
                    abuf = nb; load_tile(sbase + (uint32_t)nb * TILE_BYTES,
                                         g_Z + (size_t)it2 * TILE * D_DIM, tid);  nb = (nb + 1) % 3;
                    bb0  = nb; load_tile(sbase + (uint32_t)nb * TILE_BYTES,
                                         g_Z + (size_t)jt02 * TILE * D_DIM, tid); nb = (nb + 1) % 3;
                    asm volatile("cp.async.commit_group;" ::: "memory");
                } else if (has_quarter) {
                    // prefetch leftover quarter's A + B under this tile's compute
                    const int qjt = 56 + (blockIdx.x >> 2);
                    const int qcq = blockIdx.x & 3;
                    qa = nb;
                    load_tile(sbase + (uint32_t)nb * TILE_BYTES,
                              g_Z + (size_t)32 * TILE * D_DIM, tid);
                    nb = (nb + 1) % 3;
                    qb = nb;
                    {
                        const __half* gsrc = g_Z + ((size_t)qjt * TILE + qcq * 32) * D_DIM;
#pragma unroll
                        for (int i = 0; i < 4; ++i) {
                            int u = tid + i * 256;
                            int r2 = u >> 5, c2 = u & 31;
                            uint32_t saddr = sbase + (uint32_t)qb * TILE_BYTES
                                           + (uint32_t)r2 * ROW_BYTES + (uint32_t)c2 * 16;
                            asm volatile("cp.async.cg.shared.global [%0], [%1], 16;"
                                         :: "r"(saddr), "l"((const char*)gsrc + (size_t)u * 16));
                        }
                    }
                    asm volatile("cp.async.commit_group;" ::: "memory");
                }
            }

            const uint32_t bbase = sbase + (uint32_t)bcur * TILE_BYTES + boff;
            bcur = (bcur + 1) % 3;   // B tiles within a run rotate strictly +1

            float4 acc[2][8];
#pragma unroll
            for (int mi = 0; mi < 2; ++mi)
#pragma unroll
                for (int nt = 0; nt < 8; ++nt) acc[mi][nt] = make_float4(0.f, 0.f, 0.f, 0.f);

#pragma unroll
            for (int ks = 0; ks < 16; ++ks) {
                uint32_t bf[4][4];
#pragma unroll
                for (int bt = 0; bt < 4; ++bt)
                    ldsm_x4(bbase + (uint32_t)(bt * 16) * ROW_BYTES + (uint32_t)ks * 32, bf[bt]);
#pragma unroll
                for (int bt = 0; bt < 4; ++bt) {
                    mma16816(acc[0][2 * bt],     areg[ks],     bf[bt][0], bf[bt][2]);
                    mma16816(acc[0][2 * bt + 1], areg[ks],     bf[bt][1], bf[bt][3]);
                    mma16816(acc[1][2 * bt],     areg[ks] + 4, bf[bt][0], bf[bt][2]);
                    mma16816(acc[1][2 * bt + 1], areg[ks] + 4, bf[bt][1], bf[bt][3]);
                }
            }

            // epilogue (no barrier: warps drift; MUFU overlaps other warps' MMA)
            const bool offdiag = (jt != it);
            float colacc[16];
#pragma unroll
            for (int i = 0; i < 16; ++i) colacc[i] = 0.f;
#pragma unroll
            for (int mi = 0; mi < 2; ++mi) {
                float s0 = 0.f, s1 = 0.f;
#pragma unroll
                for (int nt = 0; nt < 8; ++nt) {
                    float4 c = acc[mi][nt];
                    float ex = ex2f(c.x), ey = ex2f(c.y);
                    float ez = ex2f(c.z), ew = ex2f(c.w);
                    s0 += ex + ey;
                    s1 += ez + ew;
                    colacc[nt * 2]     += ex + ez;
                    colacc[nt * 2 + 1] += ey + ew;
                }
                rsum[mi][0] += s0;
                rsum[mi][1] += s1;
            }
            if (offdiag) {
#pragma unroll
                for (int i = 0; i < 16; ++i) {
                    float v = colacc[i];
                    v += __shfl_xor_sync(0xffffffffu, v, 4);
                    v += __shfl_xor_sync(0xffffffffu, v, 8);
                    v += __shfl_xor_sync(0xffffffffu, v, 16);
                    colacc[i] = v;
                }
                if (lane < 4) {
                    const int cbase = jt * TILE + warp_n * 64;
#pragma unroll
                    for (int nt = 0; nt < 8; ++nt) {
                        atomicAdd(&g_denom[cbase + nt * 8 + 2 * lane],     colacc[nt * 2]);
                        atomicAdd(&g_denom[cbase + nt * 8 + 2 * lane + 1], colacc[nt * 2 + 1]);
                    }
                }
            }
        }

        // run row sums: intra-warp reduce + direct REDG (both warp_n contribute)
#pragma unroll
        for (int mi = 0; mi < 2; ++mi)
#pragma unroll
            for (int h = 0; h < 2; ++h) {
                float v = rsum[mi][h];
                v += __shfl_xor_sync(0xffffffffu, v, 1);
                v += __shfl_xor_sync(0xffffffffu, v, 2);
                if ((lane & 3) == 0)
                    atomicAdd(&g_denom[it * TILE + warp_m * 32 + mi * 16 + h * 8 + (lane >> 2)], v);
            }

        t += n;
    }

    // ---- leftover quarter-tile pass (data prefetched during last main tile) ----
    if (has_quarter) {
        const int it2 = 32;
        const int jt  = 56 + (blockIdx.x >> 2);
        const int cq  = blockIdx.x & 3;

        asm volatile("cp.async.wait_group 0;" ::: "memory");
        __syncthreads();   // quarter data visible; last tile's B reads done

        uint32_t areg[16][8];
        const uint32_t abase = sbase + (uint32_t)qa * TILE_BYTES + aoff;
#pragma unroll
        for (int ks = 0; ks < 16; ++ks) {
            ldsm_x4(abase + (uint32_t)ks * 32, areg[ks]);
            ldsm_x4(abase + 16u * ROW_BYTES + (uint32_t)ks * 32, areg[ks] + 4);
        }

        const uint32_t bq = sbase + (uint32_t)qb * TILE_BYTES
                          + (uint32_t)(warp_n * 16) * ROW_BYTES + lrow;
        float4 acc[2][2];
#pragma unroll
        for (int mi = 0; mi < 2; ++mi)
#pragma unroll
            for (int nt = 0; nt < 2; ++nt) acc[mi][nt] = make_float4(0.f, 0.f, 0.f, 0.f);

#pragma unroll
        for (int ks = 0; ks < 16; ++ks) {
            uint32_t bf[4];
            ldsm_x4(bq + (uint32_t)ks * 32, bf);
            mma16816(acc[0][0], areg[ks],     bf[0], bf[2]);
            mma16816(acc[0][1], areg[ks],     bf[1], bf[3]);
            mma16816(acc[1][0], areg[ks] + 4, bf[0], bf[2]);
            mma16816(acc[1][1], areg[ks] + 4, bf[1], bf[3]);
        }

        float colacc[4] = {0.f, 0.f, 0.f, 0.f};
        float rs[2][2]  = {{0.f, 0.f}, {0.f, 0.f}};
#pragma unroll
        for (int mi = 0; mi < 2; ++mi)
#pragma unroll
            for (int nt = 0; nt < 2; ++nt) {
                float4 c = acc[mi][nt];
                float ex = ex2f(c.x), ey = ex2f(c.y);
                float ez = ex2f(c.z), ew = ex2f(c.w);
                rs[mi][0] += ex + ey;
                rs[mi][1] += ez + ew;
                colacc[nt * 2]     += ex + ez;
                colacc[nt * 2 + 1] += ey + ew;
            }
#pragma unroll
        for (int i = 0; i < 4; ++i) {
            float v = colacc[i];
            v += __shfl_xor_sync(0xffffffffu, v, 4);
            v += __shfl_xor_sync(0xffffffffu, v, 8);
            v += __shfl_xor_sync(0xffffffffu, v, 16);
            colacc[i] = v;
        }
        if (lane < 4) {
            const int cbase = jt * TILE + cq * 32 + warp_n * 16;
#pragma unroll
            for (int g = 0; g < 2; ++g) {
                atomicAdd(&g_denom[cbase + g * 8 + 2 * lane],     colacc[g * 2]);
                atomicAdd(&g_denom[cbase + g * 8 + 2 * lane + 1], colacc[g * 2 + 1]);
            }
        }
#pragma unroll
        for (int mi = 0; mi < 2; ++mi)
#pragma unroll
            for (int h = 0; h < 2; ++h) {
                float v = rs[mi][h];
                v += __shfl_xor_sync(0xffffffffu, v, 1);
                v += __shfl_xor_sync(0xffffffffu, v, 2);
                if ((lane & 3) == 0)
                    atomicAdd(&g_denom[it2 * TILE + warp_m * 32 + mi * 16 + h * 8 + (lane >> 2)], v);
            }
    }
}

// ============ kernel 3: one pair per warp; positives + self-term removal + final sum ============
__global__ void __launch_bounds__(256) k_loss_partial(float* __restrict__ out) {
    const int wid  = threadIdx.x >> 5;
    const int lane = threadIdx.x & 31;
    const int i    = blockIdx.x * 8 + wid;         // pair 0..4095 (grid 512)

    pdl_wait();   // overlap launch ramp with gemm tail; block until gemm done

    uint4 a = ((const uint4*)(g_Z + (size_t)i * D_DIM))[lane];
    uint4 b = ((const uint4*)(g_Z + (size_t)(i + B_ROWS) * D_DIM))[lane];
    const __half2* pa = (const __half2*)&a;
    const __half2* pb = (const __half2*)&b;
    float d = 0.f, saa = 0.f, sbb = 0.f;
#pragma unroll
    for (int j = 0; j < 4; ++j) {
        float2 fa = __half22float2(pa[j]);
        float2 fb = __half22float2(pb[j]);
        d   += fa.x * fb.x + fa.y * fb.y;
        saa += fa.x * fa.x + fa.y * fa.y;
        sbb += fb.x * fb.x + fb.y * fb.y;
    }
#pragma unroll
    for (int o = 16; o; o >>= 1) {
        d   += __shfl_xor_sync(0xffffffffu, d, o);
        saa += __shfl_xor_sync(0xffffffffu, saa, o);
        sbb += __shfl_xor_sync(0xffffffffu, sbb, o);
    }
    __shared__ float sacc[8];
    if (lane == 0) {
        // Z is scaled by sqrt(2/ln2): dots are (2/ln2)x the true values
        float di = g_denom[i]          - exp2f(saa);
        float dj = g_denom[i + B_ROWS] - exp2f(sbb);
        sacc[wid] = NEG_2LN2 * d + logf(di) + logf(dj);
    }
    __syncthreads();
    if (threadIdx.x == 0) {
        float s = 0.0f;
#pragma unroll
        for (int w = 0; w < 8; ++w) s += sacc[w];
        atomicAdd(out, s * (1.0f / (float)N_TOT));
    }
}

// ============ launch ============
extern "C" void kernel_launch(void* const* d_in, const int* in_sizes, int n_in,
                              void* d_out, int out_size) {
    const float* q = (const float*)d_in[0];
    const float* p = (const float*)d_in[1];
    (void)in_sizes; (void)n_in; (void)out_size;

    static bool attr_set = false;
    if (!attr_set) {
        cudaFuncSetAttribute(k_gemm_denom, cudaFuncAttributeMaxDynamicSharedMemorySize, SMEM_TOTAL);
        attr_set = true;
    }

    k_normalize<<<N_TOT / 8, 256>>>(q, p, (float*)d_out);

    // gemm: PDL-dependent on normalize
    {
        cudaLaunchConfig_t cfg = {};
        cfg.gridDim = dim3(NCTA, 1, 1);
        cfg.blockDim = dim3(256, 1, 1);
        cfg.dynamicSmemBytes = SMEM_TOTAL;
        cfg.stream = 0;
        cudaLaunchAttribute at[1];
        at[0].id = cudaLaunchAttributeProgrammaticStreamSerialization;
        at[0].val.programmaticStreamSerializationAllowed = 1;
        cfg.attrs = at;
        cfg.numAttrs = 1;
        cudaLaunchKernelEx(&cfg, k_gemm_denom);
    }
    // loss: PDL-dependent on gemm
    {
        cudaLaunchConfig_t cfg = {};
        cfg.gridDim = dim3(512, 1, 1);
        cfg.blockDim = dim3(256, 1, 1);
        cfg.dynamicSmemBytes = 0;
        cfg.stream = 0;
        cudaLaunchAttribute at[1];
        at[0].id = cudaLaunchAttributeProgrammaticStreamSerialization;
        at[0].val.programmaticStreamSerializationAllowed = 1;
        cfg.attrs = at;
        cfg.numAttrs = 1;
        cudaLaunchKernelEx(&cfg, k_loss_partial, (float*)d_out);
    }
}